// round 1
// baseline (speedup 1.0000x reference)
#include <cuda_runtime.h>

// CRF loss: linear-domain forward scan + gold path score.
// One CTA (128 threads) per batch row. Thread j owns column j of E=exp(trans)
// as 64 packed f32x2 registers. Alpha ping-pongs in shared memory.

namespace {
constexpr int TT = 128;    // tag dim (126 tags + start + end)
constexpr int SS = 1024;   // sequence length
constexpr int NB = 256;    // batch
constexpr int START_TAG = 126;
constexpr int END_TAG = 127;
}

__device__ double g_part[NB];

__device__ __forceinline__ unsigned long long pack2f(float lo, float hi) {
    unsigned long long r;
    asm("mov.b64 %0, {%1, %2};" : "=l"(r) : "f"(lo), "f"(hi));
    return r;
}

// dot of shared alpha[0..127] with this thread's E column (packed pairs over i)
__device__ __forceinline__ float dotrow(const float* __restrict__ ar,
                                        const unsigned long long* __restrict__ E) {
    unsigned long long acc0 = 0ull, acc1 = 0ull, acc2 = 0ull, acc3 = 0ull;
    const double2* ap = reinterpret_cast<const double2*>(ar);
#pragma unroll
    for (int k = 0; k < 16; k++) {
        double2 a = ap[2 * k];
        double2 b = ap[2 * k + 1];
        unsigned long long a0 = __double_as_longlong(a.x);
        unsigned long long a1 = __double_as_longlong(a.y);
        unsigned long long b0 = __double_as_longlong(b.x);
        unsigned long long b1 = __double_as_longlong(b.y);
        asm("fma.rn.f32x2 %0, %1, %2, %0;" : "+l"(acc0) : "l"(a0), "l"(E[4 * k + 0]));
        asm("fma.rn.f32x2 %0, %1, %2, %0;" : "+l"(acc1) : "l"(a1), "l"(E[4 * k + 1]));
        asm("fma.rn.f32x2 %0, %1, %2, %0;" : "+l"(acc2) : "l"(b0), "l"(E[4 * k + 2]));
        asm("fma.rn.f32x2 %0, %1, %2, %0;" : "+l"(acc3) : "l"(b1), "l"(E[4 * k + 3]));
    }
    asm("add.rn.f32x2 %0, %0, %1;" : "+l"(acc0) : "l"(acc1));
    asm("add.rn.f32x2 %0, %0, %1;" : "+l"(acc2) : "l"(acc3));
    asm("add.rn.f32x2 %0, %0, %1;" : "+l"(acc0) : "l"(acc2));
    float lo, hi;
    asm("mov.b64 {%0, %1}, %2;" : "=f"(lo), "=f"(hi) : "l"(acc0));
    return lo + hi;
}

template <bool REN>
__device__ __forceinline__ void crf_step(const float* aread, float* awrite,
                                         const unsigned long long* E,
                                         float emv, int j, int& le, float* red) {
    float s = dotrow(aread, E);
    float v = s * __expf(emv);
    if (REN) {
        // row max -> extract exponent -> scale by 2^-ex (no MUFU)
        float m = v;
#pragma unroll
        for (int o = 16; o > 0; o >>= 1)
            m = fmaxf(m, __shfl_xor_sync(0xffffffffu, m, o));
        if ((j & 31) == 0) red[j >> 5] = m;
        __syncthreads();
        m = fmaxf(fmaxf(red[0], red[1]), fmaxf(red[2], red[3]));
        int ex = (__float_as_int(m) >> 23) - 127;
        le += ex;
        v *= __int_as_float((127 - ex) << 23);
    }
    awrite[j] = v;
    __syncthreads();
}

__global__ void __launch_bounds__(128, 2)
crf_scan_kernel(const float* __restrict__ em, const int* __restrict__ tags,
                const float* __restrict__ trans) {
    const int b = blockIdx.x;
    const int j = threadIdx.x;
    __shared__ __align__(16) float alpha[2][TT];
    __shared__ float red[8];

    const float* emb = em + (size_t)b * SS * TT;
    const int* tg = tags + b * SS;

    // E column j in registers, packed as (i, i+1) f32x2 pairs.
    unsigned long long E[64];
#pragma unroll
    for (int k = 0; k < 64; k++) {
        float e0 = __expf(trans[(2 * k) * TT + j]);
        float e1 = __expf(trans[(2 * k + 1) * TT + j]);
        E[k] = pack2f(e0, e1);
    }

    // ---- gold path score (emit gather + transition gather) ----
    float gold = 0.f;
#pragma unroll
    for (int r = 0; r < SS / TT; r++) {
        int s = r * TT + j;
        int cur = tg[s];
        int prev = (s == 0) ? START_TAG : tg[s - 1];
        gold += emb[s * TT + cur] + trans[prev * TT + cur];
    }
    if (j == 0) gold += trans[tg[SS - 1] * TT + END_TAG];

    // max of final transition row (for safe final LSE)
    float tE = trans[END_TAG * TT + j];
    float m = tE;
#pragma unroll
    for (int o = 16; o > 0; o >>= 1)
        m = fmaxf(m, __shfl_xor_sync(0xffffffffu, m, o));
    if ((j & 31) == 0) red[j >> 5] = m;
    // init alpha: exp(fv0) with fv0 = 0 at START, -1e4 elsewhere
    alpha[0][j] = (j == START_TAG) ? 1.f : 0.f;
    __syncthreads();
    const float mTE = fmaxf(fmaxf(red[0], red[1]), fmaxf(red[2], red[3]));

    // ---- linear-domain scan over t = 1..1023 ----
    int le = 0;
    float b0 = emb[1 * TT + j];
    float b1 = emb[2 * TT + j];
    float b2 = emb[3 * TT + j];
    float b3 = emb[4 * TT + j];

    float* a0p = alpha[0];
    float* a1p = alpha[1];
    for (int g = 0; g < 254; g++) {
        const int tn = 5 + 4 * g;  // prefetch next group's emissions (<=1020)
        float n0 = emb[(tn + 0) * TT + j];
        float n1 = emb[(tn + 1) * TT + j];
        float n2 = emb[(tn + 2) * TT + j];
        float n3 = emb[(tn + 3) * TT + j];
        crf_step<false>(a0p, a1p, E, b0, j, le, red);
        crf_step<false>(a1p, a0p, E, b1, j, le, red);
        crf_step<false>(a0p, a1p, E, b2, j, le, red);
        crf_step<true >(a1p, a0p, E, b3, j, le, red);
        b0 = n0; b1 = n1; b2 = n2; b3 = n3;
    }
    // buffered steps t = 1017..1020
    crf_step<false>(a0p, a1p, E, b0, j, le, red);
    crf_step<false>(a1p, a0p, E, b1, j, le, red);
    crf_step<false>(a0p, a1p, E, b2, j, le, red);
    crf_step<true >(a1p, a0p, E, b3, j, le, red);
    // tail t = 1021..1023
    crf_step<false>(a0p, a1p, E, emb[1021 * TT + j], j, le, red);
    crf_step<false>(a1p, a0p, E, emb[1022 * TT + j], j, le, red);
    crf_step<false>(a0p, a1p, E, emb[1023 * TT + j], j, le, red);
    // final alpha lives in alpha[1]

    // ---- partition = le*ln2 + mTE + log(sum_j alpha[j]*exp(tE_j - mTE)) ----
    float v = a1p[j] * __expf(tE - mTE);
    float x = v, y = gold;
#pragma unroll
    for (int o = 16; o > 0; o >>= 1) {
        x += __shfl_xor_sync(0xffffffffu, x, o);
        y += __shfl_xor_sync(0xffffffffu, y, o);
    }
    if ((j & 31) == 0) { red[j >> 5] = x; red[4 + (j >> 5)] = y; }
    __syncthreads();
    if (j == 0) {
        float sumv = red[0] + red[1] + red[2] + red[3];
        float sumg = red[4] + red[5] + red[6] + red[7];
        double part = (double)le * 0.6931471805599453 + (double)mTE + log((double)sumv);
        g_part[b] = part - (double)sumg;
    }
}

__global__ void crf_finish_kernel(float* __restrict__ out) {
    __shared__ double sd[NB];
    int t = threadIdx.x;
    sd[t] = g_part[t];
    __syncthreads();
#pragma unroll
    for (int o = NB / 2; o > 0; o >>= 1) {
        if (t < o) sd[t] += sd[t + o];
        __syncthreads();
    }
    if (t == 0) out[0] = (float)(sd[0] * (1.0 / NB));
}

extern "C" void kernel_launch(void* const* d_in, const int* in_sizes, int n_in,
                              void* d_out, int out_size) {
    const float* em = (const float*)d_in[0];     // [256,1024,128] f32
    const int* tags = (const int*)d_in[1];       // [256,1024] i32
    const float* trans = (const float*)d_in[2];  // [128,128] f32
    crf_scan_kernel<<<NB, 128>>>(em, tags, trans);
    crf_finish_kernel<<<1, NB>>>((float*)d_out);
}

// round 3
// speedup vs baseline: 1.1365x; 1.1365x over previous
#include <cuda_runtime.h>

// CRF loss: linear-domain forward scan + gold path score.
// One CTA (128 threads) per batch row. Thread j owns column j of E=exp(trans)
// as 64 packed f32x2 registers. Alpha ping-pongs in shared memory.
// Renormalization is DEFERRED: the REN step computes the row max via
// redux.sync.max.s32 (valid: values are >= 0) behind the step barrier; the
// next step folds 2^-ex into expem.

namespace {
constexpr int TT = 128;
constexpr int SS = 1024;
constexpr int NB = 256;
constexpr int START_TAG = 126;
constexpr int END_TAG = 127;
}

typedef unsigned long long ull;
__device__ double g_part[NB];

__device__ __forceinline__ ull pack2f(float lo, float hi) {
    ull r;
    asm("mov.b64 %0, {%1, %2};" : "=l"(r) : "f"(lo), "f"(hi));
    return r;
}

// dot of shared alpha[0..127] with this thread's E column; 8 accumulators.
__device__ __forceinline__ float dotrow(const float* __restrict__ ar,
                                        const ull* __restrict__ E) {
    ull acc[8];
#pragma unroll
    for (int i = 0; i < 8; i++) acc[i] = 0ull;
    const double2* ap = reinterpret_cast<const double2*>(ar);
#pragma unroll
    for (int k = 0; k < 16; k++) {
        double2 a = ap[2 * k];
        double2 b = ap[2 * k + 1];
        ull a0 = __double_as_longlong(a.x);
        ull a1 = __double_as_longlong(a.y);
        ull b0 = __double_as_longlong(b.x);
        ull b1 = __double_as_longlong(b.y);
        asm("fma.rn.f32x2 %0, %1, %2, %0;" : "+l"(acc[(4 * k + 0) & 7]) : "l"(a0), "l"(E[4 * k + 0]));
        asm("fma.rn.f32x2 %0, %1, %2, %0;" : "+l"(acc[(4 * k + 1) & 7]) : "l"(a1), "l"(E[4 * k + 1]));
        asm("fma.rn.f32x2 %0, %1, %2, %0;" : "+l"(acc[(4 * k + 2) & 7]) : "l"(b0), "l"(E[4 * k + 2]));
        asm("fma.rn.f32x2 %0, %1, %2, %0;" : "+l"(acc[(4 * k + 3) & 7]) : "l"(b1), "l"(E[4 * k + 3]));
    }
    asm("add.rn.f32x2 %0, %0, %1;" : "+l"(acc[0]) : "l"(acc[4]));
    asm("add.rn.f32x2 %0, %0, %1;" : "+l"(acc[1]) : "l"(acc[5]));
    asm("add.rn.f32x2 %0, %0, %1;" : "+l"(acc[2]) : "l"(acc[6]));
    asm("add.rn.f32x2 %0, %0, %1;" : "+l"(acc[3]) : "l"(acc[7]));
    asm("add.rn.f32x2 %0, %0, %1;" : "+l"(acc[0]) : "l"(acc[2]));
    asm("add.rn.f32x2 %0, %0, %1;" : "+l"(acc[1]) : "l"(acc[3]));
    asm("add.rn.f32x2 %0, %0, %1;" : "+l"(acc[0]) : "l"(acc[1]));
    float lo, hi;
    asm("mov.b64 {%0, %1}, %2;" : "=f"(lo), "=f"(hi) : "l"(acc[0]));
    return lo + hi;
}

template <bool REN>
__device__ __forceinline__ void crf_step(const float* __restrict__ ar,
                                         float* __restrict__ aw,
                                         const ull* __restrict__ E,
                                         float expem, int j, float* red) {
    float v = dotrow(ar, E) * expem;
    aw[j] = v;
    if (REN) {
        // v >= 0, so fp max == signed-int max on the bit patterns
        int m;
        asm volatile("redux.sync.max.s32 %0, %1, 0xffffffff;"
                     : "=r"(m) : "r"(__float_as_int(v)));
        if ((j & 31) == 0) red[j >> 5] = __int_as_float(m);
    }
    __syncthreads();
}

__global__ void __launch_bounds__(128, 2)
crf_scan_kernel(const float* __restrict__ em, const int* __restrict__ tags,
                const float* __restrict__ trans) {
    const int b = blockIdx.x;
    const int j = threadIdx.x;
    __shared__ __align__(16) float alpha[2][TT];
    __shared__ __align__(16) float red[8];

    const float* emb = em + (size_t)b * SS * TT;
    const int* tg = tags + b * SS;

    // E column j in registers, packed as (i, i+1) f32x2 pairs.
    ull E[64];
#pragma unroll
    for (int k = 0; k < 64; k++) {
        float e0 = __expf(trans[(2 * k) * TT + j]);
        float e1 = __expf(trans[(2 * k + 1) * TT + j]);
        E[k] = pack2f(e0, e1);
    }

    // ---- gold path score ----
    float gold = 0.f;
#pragma unroll
    for (int r = 0; r < SS / TT; r++) {
        int s = r * TT + j;
        int cur = tg[s];
        int prev = (s == 0) ? START_TAG : tg[s - 1];
        gold += emb[s * TT + cur] + trans[prev * TT + cur];
    }
    if (j == 0) gold += trans[tg[SS - 1] * TT + END_TAG];

    // max of final transition row (one-time)
    float tE = trans[END_TAG * TT + j];
    {
        float m = tE;
#pragma unroll
        for (int o = 16; o > 0; o >>= 1)
            m = fmaxf(m, __shfl_xor_sync(0xffffffffu, m, o));
        if ((j & 31) == 0) red[j >> 5] = m;
    }
    __syncthreads();
    const float mTE = fmaxf(fmaxf(red[0], red[1]), fmaxf(red[2], red[3]));
    __syncthreads();
    if (j < 4) red[j] = 1.0f;  // -> ex=0, scale=1 for first group
    alpha[0][j] = (j == START_TAG) ? 1.f : 0.f;
    __syncthreads();

    // ---- linear-domain scan, t = 1..1023 ----
    int le = 0;
    float b0 = emb[1 * TT + j];
    float b1 = emb[2 * TT + j];
    float b2 = emb[3 * TT + j];
    float b3 = emb[4 * TT + j];
    float* a0p = alpha[0];
    float* a1p = alpha[1];

#pragma unroll 1
    for (int g = 0; g < 254; g++) {
        // deferred renorm: consume previous group's max
        float4 r4 = *reinterpret_cast<const float4*>(red);
        float mm = fmaxf(fmaxf(r4.x, r4.y), fmaxf(r4.z, r4.w));
        int ex = (__float_as_int(mm) >> 23) - 127;
        le += ex;
        float sc = __int_as_float((127 - ex) << 23);
        float e0 = __expf(b0) * sc;
        float e1 = __expf(b1);
        float e2 = __expf(b2);
        float e3 = __expf(b3);
        const int tn = 4 * g + 5;
        float n0 = emb[(tn + 0) * TT + j];
        float n1 = emb[(tn + 1) * TT + j];
        float n2 = emb[(tn + 2) * TT + j];
        float n3 = emb[(tn + 3) * TT + j];
        crf_step<false>(a0p, a1p, E, e0, j, red);
        crf_step<false>(a1p, a0p, E, e1, j, red);
        crf_step<false>(a0p, a1p, E, e2, j, red);
        crf_step<true >(a1p, a0p, E, e3, j, red);
        b0 = n0; b1 = n1; b2 = n2; b3 = n3;
    }
    // group 255: t = 1017..1020 (buffered), prefetch tail 1021..1023
    {
        float4 r4 = *reinterpret_cast<const float4*>(red);
        float mm = fmaxf(fmaxf(r4.x, r4.y), fmaxf(r4.z, r4.w));
        int ex = (__float_as_int(mm) >> 23) - 127;
        le += ex;
        float sc = __int_as_float((127 - ex) << 23);
        float e0 = __expf(b0) * sc;
        float e1 = __expf(b1);
        float e2 = __expf(b2);
        float e3 = __expf(b3);
        float n0 = emb[1021 * TT + j];
        float n1 = emb[1022 * TT + j];
        float n2 = emb[1023 * TT + j];
        crf_step<false>(a0p, a1p, E, e0, j, red);
        crf_step<false>(a1p, a0p, E, e1, j, red);
        crf_step<false>(a0p, a1p, E, e2, j, red);
        crf_step<true >(a1p, a0p, E, e3, j, red);
        b0 = n0; b1 = n1; b2 = n2;
    }
    // tail: t = 1021..1023
    {
        float4 r4 = *reinterpret_cast<const float4*>(red);
        float mm = fmaxf(fmaxf(r4.x, r4.y), fmaxf(r4.z, r4.w));
        int ex = (__float_as_int(mm) >> 23) - 127;
        le += ex;
        float sc = __int_as_float((127 - ex) << 23);
        float e0 = __expf(b0) * sc;
        float e1 = __expf(b1);
        float e2 = __expf(b2);
        crf_step<false>(a0p, a1p, E, e0, j, red);
        crf_step<false>(a1p, a0p, E, e1, j, red);
        crf_step<false>(a0p, a1p, E, e2, j, red);
    }
    // final alpha lives in alpha[1]

    // ---- partition = le*ln2 + mTE + log(sum_j alpha[j]*exp(tE_j - mTE)) ----
    float v = a1p[j] * __expf(tE - mTE);
    float x = v, y = gold;
#pragma unroll
    for (int o = 16; o > 0; o >>= 1) {
        x += __shfl_xor_sync(0xffffffffu, x, o);
        y += __shfl_xor_sync(0xffffffffu, y, o);
    }
    if ((j & 31) == 0) { red[j >> 5] = x; red[4 + (j >> 5)] = y; }
    __syncthreads();
    if (j == 0) {
        float sumv = red[0] + red[1] + red[2] + red[3];
        float sumg = red[4] + red[5] + red[6] + red[7];
        double part = (double)le * 0.6931471805599453 + (double)mTE + log((double)sumv);
        g_part[b] = part - (double)sumg;
    }
}

__global__ void crf_finish_kernel(float* __restrict__ out) {
    __shared__ double sd[NB];
    int t = threadIdx.x;
    sd[t] = g_part[t];
    __syncthreads();
#pragma unroll
    for (int o = NB / 2; o > 0; o >>= 1) {
        if (t < o) sd[t] += sd[t + o];
        __syncthreads();
    }
    if (t == 0) out[0] = (float)(sd[0] * (1.0 / NB));
}

extern "C" void kernel_launch(void* const* d_in, const int* in_sizes, int n_in,
                              void* d_out, int out_size) {
    const float* em = (const float*)d_in[0];     // [256,1024,128] f32
    const int* tags = (const int*)d_in[1];       // [256,1024] i32
    const float* trans = (const float*)d_in[2];  // [128,128] f32
    crf_scan_kernel<<<NB, 128>>>(em, tags, trans);
    crf_finish_kernel<<<1, NB>>>((float*)d_out);
}